// round 13
// baseline (speedup 1.0000x reference)
#include <cuda_runtime.h>

// Problem constants
#define NB 16
#define NC 3
#define H 768
#define W 768
#define HS 48            // H/16
#define WS 48            // W/16
#define NPIX (HS * WS)   // 2304
#define RADIUS 8
#define NFEAT (NB * NPIX)        // 36864
#define NBLOCKS (144 * NB)       // 2304
#define PRODUCER_BLOCKS 64       // 64 * 576 == NFEAT

// exp(-(50*cd + 0.02*sd)) = exp2( -LOG2E*(50*cd + 0.02*sd) )
#define C_DOT   144.269504089f   // 2*50*log2(e)
#define C_SQ     72.134752044f   // 50*log2(e)
#define C_SP      0.028853901f   // 0.02*log2(e)

// Downsampled features: (f0, f1, f2, |f|^2) per (b, i). 576 KB scratch.
__device__ float4 g_feats[NFEAT];
// Producer-arrival counter and block-exit counter (reset by last block each
// launch -> kernel is replay-deterministic).
__device__ unsigned g_done;
__device__ unsigned g_exit;

__device__ __forceinline__ float ex2(float x) {
    float r;
    asm("ex2.approx.ftz.f32 %0, %1;" : "=f"(r) : "f"(x));
    return r;
}

// ---------------------------------------------------------------------------
// Single fused kernel. Grid (144, 16), 576 threads.
//   linear bid = bx + 144*b. Blocks bid < 64 are PRODUCERS: each thread
//   computes one downsampled feature (16x bilinear = mean of the 2x2 pixel
//   block at (16y+7, 16x+7)), fences, and the block arrives on g_done.
//   ALL blocks then issue their feats-independent out-of-band zero stores
//   (~62% of all output bytes) BEFORE spinning on g_done==64, so the wait
//   is hidden behind store drain exactly like the former PDL split.
//   Phase 2: in-band rows, EX2-folded math, streaming STG.128.
// Geometry (best measured, R5/R8): block bx handles rows i = bx + it*144;
// stride 144 == 3*WS => xi constant per block; per-thread j-invariants
// (pre-scaled fj', exponent constant CK, band mask) computed once.
// ---------------------------------------------------------------------------
__global__ void __launch_bounds__(576, 2) fused_affinity_kernel(
    const float* __restrict__ img, float* __restrict__ out) {
    const int q   = threadIdx.x;           // float4 index within row, 0..575
    const int bx  = blockIdx.x;            // 0..143
    const int b   = blockIdx.y;            // 0..15
    const int bid = bx + 144 * b;

    // ---- Producer work: blocks 0..63 compute the feature table.
    if (bid < PRODUCER_BLOCKS) {
        const int t  = bid * 576 + q;      // feature index, 0..36863
        const int fb = t / NPIX;
        const int fi_ = t - fb * NPIX;
        const int yi = fi_ / WS;
        const int xi = fi_ - yi * WS;
        const int y0 = yi * 16 + 7;
        const int x0 = xi * 16 + 7;        // odd offset -> scalar loads only

        float f[3];
#pragma unroll
        for (int c = 0; c < 3; ++c) {
            const float* p = img + ((size_t)(fb * NC + c) * H + y0) * W + x0;
            float r0 = 0.5f * (p[0] + p[1]);        // rows first,
            float r1 = 0.5f * (p[W] + p[W + 1]);    // then columns
            f[c] = 0.5f * (r0 + r1);
        }
        float sq = f[0] * f[0] + f[1] * f[1] + f[2] * f[2];
        g_feats[t] = make_float4(f[0], f[1], f[2], sq);

        __threadfence();                    // publish feats before arriving
        __syncthreads();                    // all 576 stores done
        if (q == 0) atomicAdd(&g_done, 1u);
    }

    // ---- Common indexing.
    const int j0  = q * 4;
    const int yj  = q / 12;                 // shared by the 4 j's (4 | 48)
    const int xj0 = j0 - yj * WS;
    const int xi  = bx - (bx / WS) * WS;    // constant across all 16 rows

    const int dy0 = bx / WS - yj;           // row 0's dy; +3 per row
    const float4 zero = make_float4(0.f, 0.f, 0.f, 0.f);
    float4* const optr = (float4*)(out + (((size_t)b * NPIX + bx) * NPIX)) + q;
    const size_t ostride = (size_t)144 * (NPIX / 4);   // float4s per 144 rows

    // ---- Phase 1: feats-independent zero stores (hide the producer wait).
#pragma unroll
    for (int it = 0; it < 16; ++it) {
        const int dy = dy0 + 3 * it;
        if ((unsigned)(dy + RADIUS) > 2u * RADIUS)
            __stcs(optr + it * ostride, zero);
    }

    // ---- Wait for all producers (one spinner per block).
    if (threadIdx.x == 0) {
        unsigned v;
        do {
            asm volatile("ld.global.acquire.gpu.u32 %0, [%1];"
                         : "=r"(v) : "l"(&g_done) : "memory");
        } while (v < PRODUCER_BLOCKS);
    }
    __syncthreads();                        // publish visibility block-wide

    // ---- Phase 2: in-band rows.
    const float4* __restrict__ frow = g_feats + b * NPIX;

    float fjx[4], fjy[4], fjz[4], CK[4];
    bool  ok[4];
#pragma unroll
    for (int k = 0; k < 4; ++k) {
        const int dx = xi - (xj0 + k);
        ok[k] = ((unsigned)(dx + RADIUS) <= 2u * RADIUS);
        const float4 fj = frow[j0 + k];
        fjx[k] = C_DOT * fj.x;
        fjy[k] = C_DOT * fj.y;
        fjz[k] = C_DOT * fj.z;
        CK[k]  = -C_SQ * fj.w - C_SP * (float)(dx * dx);
    }

#pragma unroll
    for (int it = 0; it < 16; ++it) {
        const int dy = dy0 + 3 * it;
        if ((unsigned)(dy + RADIUS) <= 2u * RADIUS) {
            const float4 fi = frow[bx + it * 144];
            const float  DI = -C_SQ * fi.w - C_SP * (float)(dy * dy);
            float4 v = zero;
            float* vv = (float*)&v;
#pragma unroll
            for (int k = 0; k < 4; ++k) {
                if (ok[k]) {
                    float t = fmaf(fjx[k], fi.x, CK[k]);
                    t = fmaf(fjy[k], fi.y, t);
                    t = fmaf(fjz[k], fi.z, t);
                    vv[k] = ex2(t + DI);
                }
            }
            __stcs(optr + it * ostride, v);
        }
    }

    // ---- Reset counters for the next (graph-replayed) launch.
    __syncthreads();                        // whole block done before exit-arrive
    if (threadIdx.x == 0) {
        unsigned n = atomicAdd(&g_exit, 1u);
        if (n == NBLOCKS - 1) {             // last block out resets state
            g_done = 0u;
            g_exit = 0u;
            __threadfence();
        }
    }
}

// ---------------------------------------------------------------------------
extern "C" void kernel_launch(void* const* d_in, const int* in_sizes, int n_in,
                              void* d_out, int out_size) {
    const float* img = (const float*)d_in[0];
    float* out = (float*)d_out;

    dim3 grid(144, NB);                     // 2304 blocks, 16 rows each
    fused_affinity_kernel<<<grid, 576>>>(img, out);
}

// round 14
// speedup vs baseline: 1.1182x; 1.1182x over previous
#include <cuda_runtime.h>

// Problem constants
#define NB 16
#define NC 3
#define H 768
#define W 768
#define HS 48            // H/16
#define WS 48            // W/16
#define NPIX (HS * WS)   // 2304
#define RADIUS 8

// exp(-(50*cd + 0.02*sd)) = exp2( -LOG2E*(50*cd + 0.02*sd) )
#define C_DOT   144.269504089f   // 2*50*log2(e)
#define C_SQ     72.134752044f   // 50*log2(e)
#define C_SP      0.028853901f   // 0.02*log2(e)

// Downsampled features: (f0, f1, f2, |f|^2) per (b, i). 16*2304*16B = 576 KB scratch.
__device__ float4 g_feats[NB * NPIX];

// ---------------------------------------------------------------------------
// Kernel 1: 16x bilinear downsample. Half-pixel centers => src = 16*i + 7.5,
// exact 0.5/0.5 weights => average of the 2x2 pixel block at (16y+7, 16x+7).
// Scalar loads only: x0 = 16*xi + 7 is ODD, so vector loads would misalign.
// Fires launch_dependents immediately so the PDL-chained affinity kernel
// can begin its feats-independent zero-store phase concurrently.
// ---------------------------------------------------------------------------
__global__ void resize_feats_kernel(const float* __restrict__ img) {
    asm volatile("griddepcontrol.launch_dependents;");

    int t = blockIdx.x * blockDim.x + threadIdx.x;
    if (t >= NB * NPIX) return;
    int b = t / NPIX;
    int i = t - b * NPIX;
    int yi = i / WS;
    int xi = i - yi * WS;
    int y0 = yi * 16 + 7;
    int x0 = xi * 16 + 7;

    float f[3];
#pragma unroll
    for (int c = 0; c < 3; ++c) {
        const float* p = img + ((size_t)(b * NC + c) * H + y0) * W + x0;
        // match separable resize: average rows first, then columns
        float r0 = 0.5f * (p[0] + p[1]);
        float r1 = 0.5f * (p[W] + p[W + 1]);
        f[c] = 0.5f * (r0 + r1);
    }
    float sq = f[0] * f[0] + f[1] * f[1] + f[2] * f[2];
    g_feats[t] = make_float4(f[0], f[1], f[2], sq);
}

__device__ __forceinline__ float ex2(float x) {
    float r;
    asm("ex2.approx.ftz.f32 %0, %1;" : "=f"(r) : "f"(x));
    return r;
}

// ---------------------------------------------------------------------------
// Kernel 2: affinity — converged configuration (R12).
// Grid (144, 16): block bx handles rows i = bx + it*144, it = 0..15.
// Stride 144 == 3*WS => xi constant per block.
// Phase 1 (before griddepcontrol.wait): the ~10/16 out-of-band rows per
// thread depend only on dy -> issue their zero STG.128s while the resize
// kernel is still running (PDL overlap), pre-filling the DRAM write pipe.
// Phase 2 (after wait): load fj invariants (pre-scaled fj', exponent
// constant CK, band mask) once, then in-band rows at 3 FMA + FADD + EX2
// per element with streaming STG.128.
// Replay period is DRAM-write limited: 340 MB @ ~6.5 TB/s = ~52 us.
// ---------------------------------------------------------------------------
__global__ void __launch_bounds__(576, 2) affinity_kernel(float* __restrict__ out) {
    const int q  = threadIdx.x;            // float4 index within row, 0..575
    const int bx = blockIdx.x;             // 0..143
    const int b  = blockIdx.y;             // 0..15

    const int j0  = q * 4;
    const int yj  = q / 12;                // shared by the 4 j's (4 | 48)
    const int xj0 = j0 - yj * WS;
    const int xi  = bx - (bx / WS) * WS;   // constant across all 16 rows

    const int dy0 = bx / WS - yj;          // row 0's dy; +3 per row
    const float4 zero = make_float4(0.f, 0.f, 0.f, 0.f);
    float4* const optr = (float4*)(out + (((size_t)b * NPIX + bx) * NPIX)) + q;
    const size_t ostride = (size_t)144 * (NPIX / 4);   // float4s per 144 rows

    // ---- Phase 1: feats-independent zero stores (overlaps resize via PDL).
#pragma unroll
    for (int it = 0; it < 16; ++it) {
        const int dy = dy0 + 3 * it;
        if ((unsigned)(dy + RADIUS) > 2u * RADIUS)
            __stcs(optr + it * ostride, zero);
    }

    // ---- Wait for resize's g_feats stores to be visible.
    asm volatile("griddepcontrol.wait;" ::: "memory");

    // ---- Phase 2: in-band rows.
    const float4* __restrict__ frow = g_feats + b * NPIX;

    float fjx[4], fjy[4], fjz[4], CK[4];
    bool  ok[4];
#pragma unroll
    for (int k = 0; k < 4; ++k) {
        const int dx = xi - (xj0 + k);
        ok[k] = ((unsigned)(dx + RADIUS) <= 2u * RADIUS);
        const float4 fj = frow[j0 + k];
        fjx[k] = C_DOT * fj.x;
        fjy[k] = C_DOT * fj.y;
        fjz[k] = C_DOT * fj.z;
        CK[k]  = -C_SQ * fj.w - C_SP * (float)(dx * dx);
    }

#pragma unroll
    for (int it = 0; it < 16; ++it) {
        const int dy = dy0 + 3 * it;
        if ((unsigned)(dy + RADIUS) <= 2u * RADIUS) {
            const float4 fi = frow[bx + it * 144];
            const float  DI = -C_SQ * fi.w - C_SP * (float)(dy * dy);
            float4 v = zero;
            float* vv = (float*)&v;
#pragma unroll
            for (int k = 0; k < 4; ++k) {
                if (ok[k]) {
                    float t = fmaf(fjx[k], fi.x, CK[k]);
                    t = fmaf(fjy[k], fi.y, t);
                    t = fmaf(fjz[k], fi.z, t);
                    vv[k] = ex2(t + DI);
                }
            }
            __stcs(optr + it * ostride, v);
        }
    }
}

// ---------------------------------------------------------------------------
extern "C" void kernel_launch(void* const* d_in, const int* in_sizes, int n_in,
                              void* d_out, int out_size) {
    const float* img = (const float*)d_in[0];
    float* out = (float*)d_out;

    const int nfeat = NB * NPIX;
    resize_feats_kernel<<<(nfeat + 255) / 256, 256>>>(img);

    // Affinity chained via Programmatic Dependent Launch: launches while
    // resize runs; griddepcontrol.wait inside orders the g_feats reads.
    cudaLaunchConfig_t cfg = {};
    cfg.gridDim  = dim3(144, NB);
    cfg.blockDim = dim3(576);
    cudaLaunchAttribute attr[1];
    attr[0].id = cudaLaunchAttributeProgrammaticStreamSerialization;
    attr[0].val.programmaticStreamSerializationAllowed = 1;
    cfg.attrs = attr;
    cfg.numAttrs = 1;
    cudaLaunchKernelEx(&cfg, affinity_kernel, out);
}